// round 17
// baseline (speedup 1.0000x reference)
#include <cuda_runtime.h>
#include <math.h>

#define TSTEPS 64
#define BATCH  32
#define NH     512
#define NH2    1024
#define VOCAB  32000
#define RROWS  (TSTEPS*BATCH)   // 2048
#define SELEM  (BATCH*NH)       // 16384

// ---- kStageMMA smem layout (floats) ----
#define A_H   0
#define A_L   2176              // 32*68
#define B_H   4352
#define B_L   6528
#define BUFSZ 8704              // 4 arrays * 32*68
#define CS_OFF (2*BUFSZ)        // Cs[32][33]
#define STGM_SMEM ((2*BUFSZ + 32*33) * 4)   // 73856 bytes

// ---------------------------------------------------------------------------
// Scratch (static device globals; no allocation anywhere)
// ---------------------------------------------------------------------------
__device__ __align__(16) float g_X[RROWS*NH];
__device__ __align__(16) float g_Xpre[RROWS*NH2];
__device__ __align__(16) float g_statesT[8][SELEM];   // transposed [d][b]
__device__ __align__(16) float g_hidT[RROWS*NH];      // [t][d][b]
__device__ __align__(16) float g_logits[(size_t)RROWS*VOCAB];

__device__ __forceinline__ float sigm(float x) { return 1.f / (1.f + expf(-x)); }

__device__ __forceinline__ unsigned f2tf(float f) {
    unsigned u; asm("cvt.rna.tf32.f32 %0, %1;" : "=r"(u) : "f"(f)); return u;
}
__device__ __forceinline__ float tf32f(float x) { return __uint_as_float(f2tf(x)); }

#define MMA_TF32(acc, a, b)                                               \
    asm("mma.sync.aligned.m16n8k8.row.col.f32.tf32.tf32.f32 "             \
        "{%0,%1,%2,%3},{%4,%5,%6,%7},{%8,%9},{%0,%1,%2,%3};"              \
        : "+f"(acc[0]), "+f"(acc[1]), "+f"(acc[2]), "+f"(acc[3])          \
        : "r"(a[0]), "r"(a[1]), "r"(a[2]), "r"(a[3]), "r"(b[0]), "r"(b[1]))

// ---------------------------------------------------------------------------
// Embedding gather
// ---------------------------------------------------------------------------
__global__ __launch_bounds__(128) void kEmbed(const int* __restrict__ ids,
                                              const float* __restrict__ emb) {
    int r = blockIdx.x;
    int row = ids[r];
    const float4* src = reinterpret_cast<const float4*>(emb + (size_t)row * NH);
    float4* dst = reinterpret_cast<float4*>(g_X + (size_t)r * NH);
    dst[threadIdx.x] = src[threadIdx.x];
}

// ---------------------------------------------------------------------------
// Xpre = g_X[2048,512] @ W0[0:512, 0:1024]  (64x64 tile, 4x4 micro)
// ---------------------------------------------------------------------------
__global__ __launch_bounds__(256) void kXpreGemm(const float* __restrict__ W0) {
    __shared__ __align__(16) float As[16][64];
    __shared__ __align__(16) float Bs[16][64];
    const int m0 = blockIdx.y * 64, n0 = blockIdx.x * 64;
    const int tid = threadIdx.x, tx = tid & 15, ty = tid >> 4;
    const int am = tid >> 2, ak4 = (tid & 3) * 4;
    const int bk = tid >> 4, bn4 = (tid & 15) * 4;
    float acc[4][4];
#pragma unroll
    for (int i = 0; i < 4; i++)
#pragma unroll
        for (int j = 0; j < 4; j++) acc[i][j] = 0.f;
    for (int k0 = 0; k0 < NH; k0 += 16) {
        float4 av = *reinterpret_cast<const float4*>(g_X + (size_t)(m0+am)*NH + k0 + ak4);
        As[ak4+0][am] = av.x; As[ak4+1][am] = av.y; As[ak4+2][am] = av.z; As[ak4+3][am] = av.w;
        *reinterpret_cast<float4*>(&Bs[bk][bn4]) =
            *reinterpret_cast<const float4*>(W0 + (size_t)(k0+bk)*NH2 + n0 + bn4);
        __syncthreads();
#pragma unroll
        for (int kk = 0; kk < 16; kk++) {
            float4 a = *reinterpret_cast<float4*>(&As[kk][ty*4]);
            float4 b = *reinterpret_cast<float4*>(&Bs[kk][tx*4]);
            float aa[4] = {a.x,a.y,a.z,a.w}, bb[4] = {b.x,b.y,b.z,b.w};
#pragma unroll
            for (int i = 0; i < 4; i++)
#pragma unroll
                for (int j = 0; j < 4; j++) acc[i][j] += aa[i]*bb[j];
        }
        __syncthreads();
    }
#pragma unroll
    for (int i = 0; i < 4; i++) {
        float4 st = make_float4(acc[i][0], acc[i][1], acc[i][2], acc[i][3]);
        *reinterpret_cast<float4*>(g_Xpre + (size_t)(m0+ty*4+i)*NH2 + n0 + tx*4) = st;
    }
}

// ---------------------------------------------------------------------------
// Stage kernel via tensor cores (3xTF32 split precision).
//   i == -1 : node0 (W = W0 rows 512..1023; epilogue adds Xpre, uses hp).
//   i >= 0  : edge stage, j = i+1+blockIdx.y; A = states[i]/cnt_i.
// Block: 128 thr (4 warps), tile M=32(batch) x 16 pair-cols (32 N-cols),
// K chunked by 64, double-buffered smem, in-register hi/lo split.
// C = Ah*Bh + Al*Bh + Ah*Bl  (fp32 accumulate).
// ---------------------------------------------------------------------------
__global__ __launch_bounds__(128) void kStageMMA(const float* __restrict__ Wbase,
                                                 const float* __restrict__ h0in,
                                                 int i, int t) {
    extern __shared__ float sm[];
    const int tid = threadIdx.x;
    const int lane = tid & 31, warp = tid >> 5;
    const int d0 = blockIdx.x << 4;
    int j = 0;
    const float* W;
    float inv = 1.f;
    if (i < 0) { W = Wbase; }
    else {
        j = i + 1 + blockIdx.y;
        W = Wbase + ((size_t)(i*8 + j) << 19);   // *512*1024
        inv = (i == 0) ? 1.f : 1.f / (float)i;
    }

    float4 pa[4], pb[4];

    auto loadA = [&](int k0) {
#pragma unroll
        for (int rr = 0; rr < 4; rr++) {
            const int slot = tid + (rr << 7);
            const int kk = slot >> 3, b4 = (slot & 7) << 2;
            if (i >= 0) {
                float4 v = *reinterpret_cast<const float4*>(g_statesT[i] + (k0+kk)*32 + b4);
                v.x *= inv; v.y *= inv; v.z *= inv; v.w *= inv;
                pa[rr] = v;
            } else if (t > 0) {
                float4 a = make_float4(0.f, 0.f, 0.f, 0.f);
#pragma unroll
                for (int jj = 1; jj < 8; jj++) {
                    float4 v = *reinterpret_cast<const float4*>(g_statesT[jj] + (k0+kk)*32 + b4);
                    float wg = 1.f / (float)jj;
                    a.x += v.x*wg; a.y += v.y*wg; a.z += v.z*wg; a.w += v.w*wg;
                }
                const float c7 = 1.f / 7.f;
                a.x *= c7; a.y *= c7; a.z *= c7; a.w *= c7;
                pa[rr] = a;
                if (blockIdx.x == 0)
                    *reinterpret_cast<float4*>(g_hidT + (size_t)(t-1)*SELEM + (k0+kk)*32 + b4) = a;
            } else {
                float4 a;
                a.x = h0in[(b4+0)*NH + k0 + kk];
                a.y = h0in[(b4+1)*NH + k0 + kk];
                a.z = h0in[(b4+2)*NH + k0 + kk];
                a.w = h0in[(b4+3)*NH + k0 + kk];
                pa[rr] = a;
            }
        }
    };
    auto loadB = [&](int k0) {
#pragma unroll
        for (int rr = 0; rr < 4; rr++) {
            const int slot = tid + (rr << 7);
            const int half = slot >> 8, rem = slot & 255;
            const int kr = rem >> 2, c4 = (rem & 3) << 2;
            pb[rr] = *reinterpret_cast<const float4*>(
                W + (size_t)(k0+kr)*NH2 + (half ? NH + d0 : d0) + c4);
        }
    };
    auto stash = [&](float* buf) {
#pragma unroll
        for (int rr = 0; rr < 4; rr++) {
            const int slot = tid + (rr << 7);
            {   // A
                const int kk = slot >> 3, b4 = (slot & 7) << 2;
                const float v[4] = {pa[rr].x, pa[rr].y, pa[rr].z, pa[rr].w};
#pragma unroll
                for (int m = 0; m < 4; m++) {
                    float hi = tf32f(v[m]);
                    float lo = tf32f(v[m] - hi);
                    buf[A_H + (b4+m)*68 + kk] = hi;
                    buf[A_L + (b4+m)*68 + kk] = lo;
                }
            }
            {   // B
                const int half = slot >> 8, rem = slot & 255;
                const int kr = rem >> 2, c4 = (rem & 3) << 2;
                const int nb = half*16 + c4;
                const float v[4] = {pb[rr].x, pb[rr].y, pb[rr].z, pb[rr].w};
#pragma unroll
                for (int m = 0; m < 4; m++) {
                    float hi = tf32f(v[m]);
                    float lo = tf32f(v[m] - hi);
                    buf[B_H + (nb+m)*68 + kr] = hi;
                    buf[B_L + (nb+m)*68 + kr] = lo;
                }
            }
        }
    };

    float acc[2][4];
#pragma unroll
    for (int mt = 0; mt < 2; mt++)
#pragma unroll
        for (int q = 0; q < 4; q++) acc[mt][q] = 0.f;

    const int r = lane >> 2, cq = lane & 3;
    const int n8 = warp << 3;

    auto compute = [&](const float* buf) {
#pragma unroll
        for (int kb = 0; kb < 8; kb++) {
            const int kof = kb * 8;
            unsigned ah[2][4], al[2][4], bh[2], bl[2];
#pragma unroll
            for (int mt = 0; mt < 2; mt++) {
                const int m = mt*16 + r;
                ah[mt][0] = __float_as_uint(buf[A_H + m*68     + kof + cq]);
                ah[mt][1] = __float_as_uint(buf[A_H + (m+8)*68 + kof + cq]);
                ah[mt][2] = __float_as_uint(buf[A_H + m*68     + kof + cq + 4]);
                ah[mt][3] = __float_as_uint(buf[A_H + (m+8)*68 + kof + cq + 4]);
                al[mt][0] = __float_as_uint(buf[A_L + m*68     + kof + cq]);
                al[mt][1] = __float_as_uint(buf[A_L + (m+8)*68 + kof + cq]);
                al[mt][2] = __float_as_uint(buf[A_L + m*68     + kof + cq + 4]);
                al[mt][3] = __float_as_uint(buf[A_L + (m+8)*68 + kof + cq + 4]);
            }
            const int n = n8 + r;
            bh[0] = __float_as_uint(buf[B_H + n*68 + kof + cq]);
            bh[1] = __float_as_uint(buf[B_H + n*68 + kof + cq + 4]);
            bl[0] = __float_as_uint(buf[B_L + n*68 + kof + cq]);
            bl[1] = __float_as_uint(buf[B_L + n*68 + kof + cq + 4]);
#pragma unroll
            for (int mt = 0; mt < 2; mt++) {
                MMA_TF32(acc[mt], ah[mt], bh);
                MMA_TF32(acc[mt], al[mt], bh);
                MMA_TF32(acc[mt], ah[mt], bl);
            }
        }
    };

    // pipeline: load chunk0, stash, then overlap next-chunk loads with compute
    loadA(0); loadB(0);
    stash(sm);
    __syncthreads();
#pragma unroll 1
    for (int cch = 0; cch < 8; cch++) {
        if (cch < 7) { loadA((cch+1)*64); loadB((cch+1)*64); }
        compute(sm + (cch & 1) * BUFSZ);
        if (cch < 7) {
            stash(sm + ((cch+1) & 1) * BUFSZ);
            __syncthreads();
        }
    }

    // ---- epilogue: stage C through smem, pair (c,h) columns, gate math
    float* Cs = sm + CS_OFF;   // [32][33]
    Cs[r*33      + n8 + 2*cq    ] = acc[0][0];
    Cs[r*33      + n8 + 2*cq + 1] = acc[0][1];
    Cs[(r+8)*33  + n8 + 2*cq    ] = acc[0][2];
    Cs[(r+8)*33  + n8 + 2*cq + 1] = acc[0][3];
    Cs[(16+r)*33 + n8 + 2*cq    ] = acc[1][0];
    Cs[(16+r)*33 + n8 + 2*cq + 1] = acc[1][1];
    Cs[(24+r)*33 + n8 + 2*cq    ] = acc[1][2];
    Cs[(24+r)*33 + n8 + 2*cq + 1] = acc[1][3];
    __syncthreads();

#pragma unroll
    for (int q = 0; q < 4; q++) {
        const int item = tid + (q << 7);
        const int b = item & 31, dd = item >> 5;
        const int d = d0 + dd;
        const float cval = Cs[b*33 + dd];
        const float hval = Cs[b*33 + 16 + dd];
        if (i < 0) {
            const float* xp = g_Xpre + (size_t)t * BATCH * NH2;
            float cc = cval + xp[b*NH2 + d];
            float hh = hval + xp[b*NH2 + NH + d];
            float hp;
            if (t == 0) hp = h0in[b*NH + d];
            else {
                hp = 0.f;
#pragma unroll
                for (int jj = 1; jj < 8; jj++)
                    hp += g_statesT[jj][d*32 + b] * (1.f / (float)jj);
                hp *= (1.f / 7.f);
            }
            g_statesT[0][d*32 + b] = hp + sigm(cc) * (tanhf(hh) - hp);
        } else {
            float sp = g_statesT[i][d*32 + b] * inv;
            float act;
            if (j == 1 || j == 4)      act = tanhf(hval);
            else if (j == 2 || j == 5) act = fmaxf(hval, 0.f);
            else if (j == 3 || j == 6) act = sigm(hval);
            else                       act = hval;   // j == 7 identity
            float s = sp + sigm(cval) * (act - sp);
            if (i == 0) g_statesT[j][d*32 + b] = s;
            else        g_statesT[j][d*32 + b] += s;
        }
    }
}

// ---------------------------------------------------------------------------
// Final avg: write g_hidT[63] and last_h output (row-major [b][d])
// ---------------------------------------------------------------------------
__global__ __launch_bounds__(256) void kAvgFinal(float* __restrict__ lastOut) {
    int idx = blockIdx.x * 256 + threadIdx.x;   // = d*32 + b
    float s = 0.f;
#pragma unroll
    for (int jj = 1; jj < 8; jj++) s += g_statesT[jj][idx] * (1.f / (float)jj);
    s *= (1.f / 7.f);
    g_hidT[(size_t)(TSTEPS-1) * SELEM + idx] = s;
    int d = idx >> 5, b = idx & 31;
    lastOut[b * NH + d] = s;
}

// ---------------------------------------------------------------------------
// Decoder via tensor cores: mma.sync.m16n8k8 tf32 (single pass).
// ---------------------------------------------------------------------------
__global__ __launch_bounds__(256) void kDecMMA(const float* __restrict__ emb,
                                               const float* __restrict__ bias) {
    __shared__ float As[128][36];
    __shared__ float Bs[64][36];
    const int n0 = blockIdx.x << 6, m0 = blockIdx.y << 7;
    const int tRow0 = m0 >> 5;
    const int tid = threadIdx.x;
    const int warp = tid >> 5, lane = tid & 31;
    const int warpM = warp >> 1, warpN = warp & 1;
    const int r = lane >> 2, c = lane & 3;

    float acc[2][4][4];
#pragma unroll
    for (int mt = 0; mt < 2; mt++)
#pragma unroll
        for (int nt = 0; nt < 4; nt++)
#pragma unroll
            for (int q = 0; q < 4; q++) acc[mt][nt][q] = 0.f;

    for (int k0 = 0; k0 < NH; k0 += 32) {
#pragma unroll
        for (int rep = 0; rep < 4; rep++) {
            int slot = tid + rep*256;
            int tg = slot >> 8;
            int rem = slot & 255;
            int kk = rem >> 3;
            int b4 = (rem & 7) << 2;
            float4 v = *reinterpret_cast<const float4*>(
                g_hidT + (size_t)(tRow0 + tg)*SELEM + (size_t)(k0+kk)*32 + b4);
            int m = tg*32 + b4;
            As[m+0][kk] = tf32f(v.x);
            As[m+1][kk] = tf32f(v.y);
            As[m+2][kk] = tf32f(v.z);
            As[m+3][kk] = tf32f(v.w);
        }
#pragma unroll
        for (int rep = 0; rep < 2; rep++) {
            int slot = tid + rep*256;
            int n = slot >> 3;
            int k4 = (slot & 7) << 2;
            float4 v = __ldg(reinterpret_cast<const float4*>(
                emb + (size_t)(n0+n)*NH + k0 + k4));
            float4 w;
            w.x = tf32f(v.x); w.y = tf32f(v.y); w.z = tf32f(v.z); w.w = tf32f(v.w);
            *reinterpret_cast<float4*>(&Bs[n][k4]) = w;
        }
        __syncthreads();

#pragma unroll
        for (int kb = 0; kb < 32; kb += 8) {
            unsigned a[2][4], b[4][2];
#pragma unroll
            for (int mt = 0; mt < 2; mt++) {
                int m = warpM*32 + mt*16 + r;
                a[mt][0] = __float_as_uint(As[m  ][kb + c]);
                a[mt][1] = __float_as_uint(As[m+8][kb + c]);
                a[mt][2] = __float_as_uint(As[m  ][kb + c + 4]);
                a[mt][3] = __float_as_uint(As[m+8][kb + c + 4]);
            }
#pragma unroll
            for (int nt = 0; nt < 4; nt++) {
                int n = warpN*32 + nt*8 + r;
                b[nt][0] = __float_as_uint(Bs[n][kb + c]);
                b[nt][1] = __float_as_uint(Bs[n][kb + c + 4]);
            }
#pragma unroll
            for (int mt = 0; mt < 2; mt++)
#pragma unroll
                for (int nt = 0; nt < 4; nt++) {
                    asm("mma.sync.aligned.m16n8k8.row.col.f32.tf32.tf32.f32 "
                        "{%0,%1,%2,%3},{%4,%5,%6,%7},{%8,%9},{%0,%1,%2,%3};"
                        : "+f"(acc[mt][nt][0]), "+f"(acc[mt][nt][1]),
                          "+f"(acc[mt][nt][2]), "+f"(acc[mt][nt][3])
                        : "r"(a[mt][0]), "r"(a[mt][1]), "r"(a[mt][2]), "r"(a[mt][3]),
                          "r"(b[nt][0]), "r"(b[nt][1]));
                }
        }
        __syncthreads();
    }

#pragma unroll
    for (int mt = 0; mt < 2; mt++) {
        int m = m0 + warpM*32 + mt*16 + r;
#pragma unroll
        for (int nt = 0; nt < 4; nt++) {
            int n = n0 + warpN*32 + nt*8 + 2*c;
            float2 bz = *reinterpret_cast<const float2*>(bias + n);
            float2 lo = make_float2(acc[mt][nt][0] + bz.x, acc[mt][nt][1] + bz.y);
            float2 hi = make_float2(acc[mt][nt][2] + bz.x, acc[mt][nt][3] + bz.y);
            *reinterpret_cast<float2*>(g_logits + (size_t)m * VOCAB + n)     = lo;
            *reinterpret_cast<float2*>(g_logits + (size_t)(m+8) * VOCAB + n) = hi;
        }
    }
}

// ---------------------------------------------------------------------------
// Online log-softmax per row
// ---------------------------------------------------------------------------
__global__ __launch_bounds__(256) void kSoftmax(float* __restrict__ out) {
    const int r = blockIdx.x;
    const float* __restrict__ row = g_logits + (size_t)r * VOCAB;
    float m = -INFINITY, s = 0.f;
    for (int v = threadIdx.x; v < VOCAB; v += 256) {
        float x = row[v];
        if (x > m) { s = s * expf(m - x) + 1.f; m = x; }
        else       { s += expf(x - m); }
    }
    __shared__ float sm[256], ss[256];
    sm[threadIdx.x] = m; ss[threadIdx.x] = s;
    __syncthreads();
    for (int st = 128; st > 0; st >>= 1) {
        if (threadIdx.x < st) {
            float m2 = sm[threadIdx.x + st], s2 = ss[threadIdx.x + st];
            float m1 = sm[threadIdx.x],      s1 = ss[threadIdx.x];
            float M = fmaxf(m1, m2);
            sm[threadIdx.x] = M;
            ss[threadIdx.x] = s1 * expf(m1 - M) + s2 * expf(m2 - M);
        }
        __syncthreads();
    }
    const float lse = sm[0] + logf(ss[0]);
    float* __restrict__ orow = out + (size_t)r * VOCAB;
    for (int v = threadIdx.x; v < VOCAB; v += 256)
        orow[v] = row[v] - lse;
}

// ---------------------------------------------------------------------------
// Launch
// ---------------------------------------------------------------------------
extern "C" void kernel_launch(void* const* d_in, const int* in_sizes, int n_in,
                              void* d_out, int out_size) {
    const int*   ids  = (const int*)  d_in[0];   // [64,32]
    const float* h0   = (const float*)d_in[1];   // [1,32,512]
    const float* emb  = (const float*)d_in[2];   // [32000,512]
    const float* W0   = (const float*)d_in[3];   // [1024,1024]
    const float* Ws   = (const float*)d_in[4];   // [8,8,512,1024]
    const float* bias = (const float*)d_in[5];   // [32000]
    float* out = (float*)d_out;                  // [64,32,32000] ++ [1,32,512]

    cudaFuncSetAttribute(kStageMMA, cudaFuncAttributeMaxDynamicSharedMemorySize, STGM_SMEM);

    kEmbed<<<RROWS, 128>>>(ids, emb);
    kXpreGemm<<<dim3(NH2/64, RROWS/64), 256>>>(W0);

    const float* W0h = W0 + (size_t)NH * NH2;
    for (int t = 0; t < TSTEPS; t++) {
        kStageMMA<<<dim3(32, 1), 128, STGM_SMEM>>>(W0h, h0, -1, t);
        for (int i = 0; i < 7; i++)
            kStageMMA<<<dim3(32, 7 - i), 128, STGM_SMEM>>>(Ws, nullptr, i, t);
    }
    kAvgFinal<<<64, 256>>>(out + (size_t)RROWS * VOCAB);

    kDecMMA<<<dim3(VOCAB/64, RROWS/128), 256>>>(emb, bias);
    kSoftmax<<<RROWS, 256>>>(out);
}